// round 7
// baseline (speedup 1.0000x reference)
#include <cuda_runtime.h>
#include <cstdint>

// GRU over T2=256 steps; 4096 independent rows. 128 persistent CTAs x 256 thr,
// 32 rows/CTA. Weights SMEM-resident, math fp32 via packed fma.rn.f32x2.
// Round 7: LDS.128 broadcast g-loads, (c,c+64) col pairing, split state slabs,
// 2 barriers/step.

#define T2V 256
#define DV  64
#define RR  32
#define NCTA 128
#define NT  256
#define GS  36   // stride (floats) for broadcast-read slabs (div 4 -> LDS.128 ok)
#define GS2 34   // stride for column-accessed slabs (2-way conflicts only)

// SMEM float offsets
#define OFF_WRZ 0                         // 128*64 float2 (Wr,Wz interleaved) = 16384 floats
#define OFF_WH  (16384)                   // 128*64
#define OFF_GX0 (OFF_WH  + 128*64)        // 64*GS  x_t slab, parity 0
#define OFF_GX1 (OFF_GX0 + 64*GS)         // 64*GS  x_t slab, parity 1
#define OFF_GH  (OFF_GX1 + 64*GS)         // 64*GS  h^T        (phase-1 k>=64)
#define OFF_GHR (OFF_GH  + 64*GS)         // 64*GS  (h*r)^T    (phase-2 k>=64)
#define OFF_HB  (OFF_GHR + 64*GS)         // 64*GS2 h[c][row]
#define OFF_ZB  (OFF_HB  + 64*GS2)        // 64*GS2 z[c][row]
#define SMEM_FLOATS (OFF_ZB + 64*GS2)
#define SMEM_BYTES  (SMEM_FLOATS * 4)

typedef unsigned long long ull;

__device__ __forceinline__ ull pk2(float lo, float hi) {
    ull r;
    asm("mov.b64 %0, {%1, %2};" : "=l"(r) : "f"(lo), "f"(hi));
    return r;
}
__device__ __forceinline__ float2 upk2(ull v) {
    float2 f;
    asm("mov.b64 {%0, %1}, %2;" : "=f"(f.x), "=f"(f.y) : "l"(v));
    return f;
}
__device__ __forceinline__ void ffma2(ull& d, ull a, ull b) {
    asm("fma.rn.f32x2 %0, %1, %2, %0;" : "+l"(d) : "l"(a), "l"(b));
}
__device__ __forceinline__ ull dl(double d) { return __double_as_longlong(d); }

// sigmoid via ex2.approx + rcp.approx : ~1e-6 abs err
__device__ __forceinline__ float fsig(float x) {
    float e;
    asm("ex2.approx.f32 %0, %1;" : "=f"(e) : "f"(x * -1.4426950408889634f));
    float r;
    asm("rcp.approx.f32 %0, %1;" : "=f"(r) : "f"(1.0f + e));
    return r;
}
__device__ __forceinline__ float ftanh_(float x) {
    return fmaf(2.0f, fsig(2.0f * x), -1.0f);
}

__global__ void __launch_bounds__(NT, 1)
gru4d_kernel(const float* __restrict__ x,
             const float* __restrict__ kh,
             const float* __restrict__ kr,
             const float* __restrict__ kz,
             const float* __restrict__ bh,
             const float* __restrict__ br,
             const float* __restrict__ bz,
             float* __restrict__ out) {
    extern __shared__ float sm[];
    float2* sWrz = (float2*)(sm + OFF_WRZ);   // [k][c] -> (Wr[k][c], Wz[k][c])
    float*  sWh  = sm + OFF_WH;               // [k][c]
    float*  sgh  = sm + OFF_GH;
    float*  sghr = sm + OFF_GHR;
    float*  shb  = sm + OFF_HB;
    float*  szb  = sm + OFF_ZB;

    const int tid  = threadIdx.x;
    const int c    = tid & 63;     // output column (r-col c, z-col c; phase2 col c)
    const int rs   = tid >> 6;     // row slot
    const int rs8  = rs * 8;       // rows rs8 .. rs8+7
    const int row0 = blockIdx.x * RR;
    const size_t rstride = (size_t)T2V * DV;

    // ---- stage weights ----
    for (int idx = tid; idx < 128 * 64; idx += NT) {
        sWrz[idx] = make_float2(kr[idx], kz[idx]);   // idx = k*64 + c2
        sWh[idx]  = kh[idx];
    }

    const float brc = br[c], bzc = bz[c], bhq = bh[c];

    // ---- init: h0 = x[:,:,0,:] -> shb & sgh; x[:,:,1,:] -> sgx parity 1 ----
    {
        float* sgx1 = sm + OFF_GX1;
        const float* xp0 = x + (size_t)(row0 + rs8) * rstride + c;
        #pragma unroll
        for (int i = 0; i < 8; i++) {
            int row = rs8 + i;
            float h0v = xp0[(size_t)i * rstride];
            float x1v = xp0[(size_t)i * rstride + DV];
            shb[c * GS2 + row] = h0v;
            sgh[c * GS  + row] = h0v;
            sgx1[c * GS + row] = x1v;
        }
    }
    __syncthreads();

    for (int t = 1; t < T2V; ++t) {
        float* sgx = sm + ((t & 1) ? OFF_GX1 : OFF_GX0);

        // ---- prefetch x_{t+1} (global; hidden under phase-1) ----
        float xv[8];
        if (t < T2V - 1) {
            const float* xp = x + (size_t)(row0 + rs8) * rstride
                                + (size_t)(t + 1) * DV + c;
            #pragma unroll
            for (int i = 0; i < 8; i++) xv[i] = xp[(size_t)i * rstride];
        }

        // ========== phase 1: r|z pre-acts (K = 64 xt + 64 h) ==========
        ull acc[4][2];
        #pragma unroll
        for (int i = 0; i < 4; i++) { acc[i][0] = pk2(brc, brc); acc[i][1] = pk2(bzc, bzc); }

        #pragma unroll 4
        for (int k = 0; k < 64; k++) {                 // xt part
            float2 w = sWrz[k * 64 + c];
            ull w0 = pk2(w.x, w.x);
            ull w1 = pk2(w.y, w.y);
            double2 ga = *(const double2*)&sgx[k * GS + rs8];      // rows rs8..+3
            double2 gb = *(const double2*)&sgx[k * GS + rs8 + 4];  // rows +4..+7
            ffma2(acc[0][0], dl(ga.x), w0); ffma2(acc[0][1], dl(ga.x), w1);
            ffma2(acc[1][0], dl(ga.y), w0); ffma2(acc[1][1], dl(ga.y), w1);
            ffma2(acc[2][0], dl(gb.x), w0); ffma2(acc[2][1], dl(gb.x), w1);
            ffma2(acc[3][0], dl(gb.y), w0); ffma2(acc[3][1], dl(gb.y), w1);
        }
        #pragma unroll 4
        for (int k = 0; k < 64; k++) {                 // h part (weight rows 64+k)
            float2 w = sWrz[(64 + k) * 64 + c];
            ull w0 = pk2(w.x, w.x);
            ull w1 = pk2(w.y, w.y);
            double2 ga = *(const double2*)&sgh[k * GS + rs8];
            double2 gb = *(const double2*)&sgh[k * GS + rs8 + 4];
            ffma2(acc[0][0], dl(ga.x), w0); ffma2(acc[0][1], dl(ga.x), w1);
            ffma2(acc[1][0], dl(ga.y), w0); ffma2(acc[1][1], dl(ga.y), w1);
            ffma2(acc[2][0], dl(gb.x), w0); ffma2(acc[2][1], dl(gb.x), w1);
            ffma2(acc[3][0], dl(gb.y), w0); ffma2(acc[3][1], dl(gb.y), w1);
        }

        // ---- epilogue 1 (no barrier needed before it): r,z sigmoid; write h*r, z ----
        #pragma unroll
        for (int i = 0; i < 4; i++) {
            int row = rs8 + 2 * i;
            float2 ra = upk2(acc[i][0]);
            float2 za = upk2(acc[i][1]);
            float r0 = fsig(ra.x), r1 = fsig(ra.y);
            float z0 = fsig(za.x), z1 = fsig(za.y);
            float2 h2 = *(const float2*)&shb[c * GS2 + row];
            *(float2*)&sghr[c * GS + row] = make_float2(h2.x * r0, h2.y * r1);
            *(float2*)&szb[c * GS2 + row] = make_float2(z0, z1);
        }
        __syncthreads();   // (h*r, z) published

        // ========== phase 2: h_cand pre-act (K = 64 xt + 64 h*r) ==========
        ull a2[4];
        #pragma unroll
        for (int i = 0; i < 4; i++) a2[i] = pk2(bhq, bhq);

        #pragma unroll 4
        for (int k = 0; k < 64; k++) {                 // xt part
            float w = sWh[k * 64 + c];
            ull wb = pk2(w, w);
            double2 ga = *(const double2*)&sgx[k * GS + rs8];
            double2 gb = *(const double2*)&sgx[k * GS + rs8 + 4];
            ffma2(a2[0], dl(ga.x), wb);
            ffma2(a2[1], dl(ga.y), wb);
            ffma2(a2[2], dl(gb.x), wb);
            ffma2(a2[3], dl(gb.y), wb);
        }
        #pragma unroll 4
        for (int k = 0; k < 64; k++) {                 // h*r part
            float w = sWh[(64 + k) * 64 + c];
            ull wb = pk2(w, w);
            double2 ga = *(const double2*)&sghr[k * GS + rs8];
            double2 gb = *(const double2*)&sghr[k * GS + rs8 + 4];
            ffma2(a2[0], dl(ga.x), wb);
            ffma2(a2[1], dl(ga.y), wb);
            ffma2(a2[2], dl(gb.x), wb);
            ffma2(a2[3], dl(gb.y), wb);
        }

        // ---- epilogue 2: tanh + blend; publish h (shb + sgh) and x_{t+1} ----
        #pragma unroll
        for (int i = 0; i < 4; i++) {
            int row = rs8 + 2 * i;
            float2 pa = upk2(a2[i]);
            float hc0 = ftanh_(pa.x);
            float hc1 = ftanh_(pa.y);
            float2 z2 = *(const float2*)&szb[c * GS2 + row];
            float2 h2 = *(const float2*)&shb[c * GS2 + row];
            float hn0 = fmaf(z2.x, hc0 - h2.x, h2.x);
            float hn1 = fmaf(z2.y, hc1 - h2.y, h2.y);
            *(float2*)&shb[c * GS2 + row] = make_float2(hn0, hn1);
            *(float2*)&sgh[c * GS  + row] = make_float2(hn0, hn1);
        }
        if (t < T2V - 1) {
            float* sgxn = sm + (((t + 1) & 1) ? OFF_GX1 : OFF_GX0);
            #pragma unroll
            for (int i = 0; i < 4; i++) {
                *(float2*)&sgxn[c * GS + rs8 + 2 * i] =
                    make_float2(xv[2 * i], xv[2 * i + 1]);
            }
        }
        __syncthreads();   // state for step t+1 published
    }

    // ---- write h_final (coalesced over c) ----
    #pragma unroll
    for (int i = 0; i < 8; i++) {
        int row = rs8 + i;
        out[(size_t)(row0 + row) * DV + c] = shb[c * GS2 + row];
    }
}

extern "C" void kernel_launch(void* const* d_in, const int* in_sizes, int n_in,
                              void* d_out, int out_size) {
    const float* x  = (const float*)d_in[0];
    const float* kh = (const float*)d_in[1];
    const float* kr = (const float*)d_in[2];
    const float* kz = (const float*)d_in[3];
    const float* bh = (const float*)d_in[4];
    const float* br = (const float*)d_in[5];
    const float* bz = (const float*)d_in[6];
    float* out = (float*)d_out;

    static bool attr_set = false;
    if (!attr_set) {
        cudaFuncSetAttribute(gru4d_kernel,
                             cudaFuncAttributeMaxDynamicSharedMemorySize,
                             SMEM_BYTES);
        attr_set = true;
    }
    gru4d_kernel<<<NCTA, NT, SMEM_BYTES>>>(x, kh, kr, kz, bh, br, bz, out);
}

// round 10
// speedup vs baseline: 1.0388x; 1.0388x over previous
#include <cuda_runtime.h>
#include <cstdint>

// GRU over T2=256 steps; 4096 independent rows. 128 persistent CTAs x 256 thr,
// 32 rows/CTA. Round 8: 4x4 thread tiles, lane-distributed LDS fragments
// (no broadcast waste), fp32 math via packed fma.rn.f32x2.

#define T2V 256
#define DV  64
#define NCTA 128
#define NT  256
#define GSL 32                     // slab stride floats (128B rows, conflict-free)

// SMEM float offsets
#define OFF_WP1 0                          // 128*128: [k][o] o<64->Wr[k][o], o>=64->Wz[k][o-64]
#define OFF_WH  (128*128)                  // 128*64
#define OFF_GX0 (OFF_WH  + 128*64)         // 64*GSL  x_t slab parity 0
#define OFF_GX1 (OFF_GX0 + 64*GSL)         // 64*GSL  x_t slab parity 1
#define OFF_GH  (OFF_GX1 + 64*GSL)         // 64*GSL  h^T
#define OFF_GHR (OFF_GH  + 64*GSL)         // 64*GSL  (h*r)^T
#define OFF_HB  (OFF_GHR + 64*GSL)         // 64*GSL  h[c][row]
#define OFF_ZB  (OFF_HB  + 64*GSL)         // 64*GSL  z[c][row]
#define SMEM_FLOATS (OFF_ZB + 64*GSL)
#define SMEM_BYTES  (SMEM_FLOATS * 4)

typedef unsigned long long ull;

__device__ __forceinline__ ull pk2(float lo, float hi) {
    ull r;
    asm("mov.b64 %0, {%1, %2};" : "=l"(r) : "f"(lo), "f"(hi));
    return r;
}
__device__ __forceinline__ float2 upk2(ull v) {
    float2 f;
    asm("mov.b64 {%0, %1}, %2;" : "=f"(f.x), "=f"(f.y) : "l"(v));
    return f;
}
__device__ __forceinline__ void ffma2(ull& d, ull a, ull b) {
    asm("fma.rn.f32x2 %0, %1, %2, %0;" : "+l"(d) : "l"(a), "l"(b));
}
__device__ __forceinline__ ull dl(double d) { return __double_as_longlong(d); }

// sigmoid via ex2.approx + rcp.approx : ~1e-6 abs err
__device__ __forceinline__ float fsig(float x) {
    float e;
    asm("ex2.approx.f32 %0, %1;" : "=f"(e) : "f"(x * -1.4426950408889634f));
    float r;
    asm("rcp.approx.f32 %0, %1;" : "=f"(r) : "f"(1.0f + e));
    return r;
}
__device__ __forceinline__ float ftanh_(float x) {
    return fmaf(2.0f, fsig(2.0f * x), -1.0f);
}

__global__ void __launch_bounds__(NT, 1)
gru4d_kernel(const float* __restrict__ x,
             const float* __restrict__ kh,
             const float* __restrict__ kr,
             const float* __restrict__ kz,
             const float* __restrict__ bh,
             const float* __restrict__ br,
             const float* __restrict__ bz,
             float* __restrict__ out) {
    extern __shared__ float sm[];
    float* sWp1 = sm + OFF_WP1;
    float* sWh  = sm + OFF_WH;
    float* sgh  = sm + OFF_GH;
    float* sghr = sm + OFF_GHR;
    float* shb  = sm + OFF_HB;
    float* szb  = sm + OFF_ZB;

    const int tid  = threadIdx.x;
    const int w    = tid >> 5;        // warp 0..7
    const int lane = tid & 31;
    const int rg4  = (lane >> 2) * 4; // row base: 0,4,...,28 (8 groups)
    const int cg   = lane & 3;        // col group within warp
    const int obase  = 16 * w + 4 * cg;   // phase-1 cols obase..obase+3 (of 128)
    const int c2base = 8 * w + 2 * cg;    // phase-2 cols c2base..c2base+1 (of 64)
    const int row0 = blockIdx.x * 32;
    const size_t rstride = (size_t)T2V * DV;

    // ---- stage weights ----
    for (int idx = tid; idx < 128 * 128; idx += NT) {
        int k = idx >> 7, o = idx & 127;
        sWp1[idx] = (o < 64) ? kr[k * 64 + o] : kz[k * 64 + (o - 64)];
    }
    for (int idx = tid; idx < 128 * 64; idx += NT) sWh[idx] = kh[idx];

    // ---- biases ----
    float bb[4];
    #pragma unroll
    for (int j = 0; j < 4; j++) {
        int o = obase + j;
        bb[j] = (o < 64) ? br[o] : bz[o - 64];
    }
    const float bh0 = bh[c2base], bh1 = bh[c2base + 1];

    // ---- init: h0 = x[:,:,0,:]; stage x[:,:,1,:] into parity-1 slab ----
    {
        float* sgx1 = sm + OFF_GX1;
        const float* xp0 = x + (size_t)(row0 + rg4) * rstride + c2base;
        #pragma unroll
        for (int j = 0; j < 2; j++) {
            int c = c2base + j;
            #pragma unroll
            for (int i = 0; i < 4; i++) {
                float h0v = xp0[(size_t)i * rstride + j];
                float x1v = xp0[(size_t)i * rstride + DV + j];
                shb[c * GSL + rg4 + i]  = h0v;
                sgh[c * GSL + rg4 + i]  = h0v;
                sgx1[c * GSL + rg4 + i] = x1v;
            }
        }
    }
    __syncthreads();

    for (int t = 1; t < T2V; ++t) {
        float* sgx = sm + ((t & 1) ? OFF_GX1 : OFF_GX0);

        // ---- prefetch x_{t+1} (hidden under phase-1 compute) ----
        float xv[2][4];
        if (t < T2V - 1) {
            const float* xp = x + (size_t)(row0 + rg4) * rstride
                                + (size_t)(t + 1) * DV + c2base;
            #pragma unroll
            for (int j = 0; j < 2; j++)
                #pragma unroll
                for (int i = 0; i < 4; i++)
                    xv[j][i] = xp[(size_t)i * rstride + j];
        }

        // ========== phase 1: r|z pre-acts (K = 64 xt + 64 h) ==========
        ull acc[4][2];
        #pragma unroll
        for (int j = 0; j < 4; j++) {
            acc[j][0] = pk2(bb[j], bb[j]);
            acc[j][1] = pk2(bb[j], bb[j]);
        }

        #pragma unroll 8
        for (int k = 0; k < 64; k++) {              // xt part (weight rows k)
            float4 wv = *(const float4*)&sWp1[k * 128 + obase];
            double2 gd = *(const double2*)&sgx[k * GSL + rg4];
            ull ga = dl(gd.x), gb = dl(gd.y);
            ull W0 = pk2(wv.x, wv.x), W1 = pk2(wv.y, wv.y);
            ull W2 = pk2(wv.z, wv.z), W3 = pk2(wv.w, wv.w);
            ffma2(acc[0][0], ga, W0); ffma2(acc[0][1], gb, W0);
            ffma2(acc[1][0], ga, W1); ffma2(acc[1][1], gb, W1);
            ffma2(acc[2][0], ga, W2); ffma2(acc[2][1], gb, W2);
            ffma2(acc[3][0], ga, W3); ffma2(acc[3][1], gb, W3);
        }
        #pragma unroll 8
        for (int k = 0; k < 64; k++) {              // h part (weight rows 64+k)
            float4 wv = *(const float4*)&sWp1[(64 + k) * 128 + obase];
            double2 gd = *(const double2*)&sgh[k * GSL + rg4];
            ull ga = dl(gd.x), gb = dl(gd.y);
            ull W0 = pk2(wv.x, wv.x), W1 = pk2(wv.y, wv.y);
            ull W2 = pk2(wv.z, wv.z), W3 = pk2(wv.w, wv.w);
            ffma2(acc[0][0], ga, W0); ffma2(acc[0][1], gb, W0);
            ffma2(acc[1][0], ga, W1); ffma2(acc[1][1], gb, W1);
            ffma2(acc[2][0], ga, W2); ffma2(acc[2][1], gb, W2);
            ffma2(acc[3][0], ga, W3); ffma2(acc[3][1], gb, W3);
        }

        // ---- epilogue 1: sigmoid; r-warps (0-3) write h*r, z-warps (4-7) write z ----
        if (w < 4) {
            #pragma unroll
            for (int j = 0; j < 4; j++) {
                int c = obase + j;                        // r-gate col (<64)
                float2 p0 = upk2(acc[j][0]);
                float2 p1 = upk2(acc[j][1]);
                float s0 = fsig(p0.x), s1 = fsig(p0.y);
                float s2 = fsig(p1.x), s3 = fsig(p1.y);
                float4 h4 = *(const float4*)&shb[c * GSL + rg4];
                *(float4*)&sghr[c * GSL + rg4] =
                    make_float4(h4.x * s0, h4.y * s1, h4.z * s2, h4.w * s3);
            }
        } else {
            #pragma unroll
            for (int j = 0; j < 4; j++) {
                int c = obase - 64 + j;                   // z-gate col
                float2 p0 = upk2(acc[j][0]);
                float2 p1 = upk2(acc[j][1]);
                *(float4*)&szb[c * GSL + rg4] =
                    make_float4(fsig(p0.x), fsig(p0.y), fsig(p1.x), fsig(p1.y));
            }
        }
        __syncthreads();   // (h*r, z) published

        // ========== phase 2: h_cand pre-act (K = 64 xt + 64 h*r) ==========
        ull a2[2][2];
        a2[0][0] = pk2(bh0, bh0); a2[0][1] = pk2(bh0, bh0);
        a2[1][0] = pk2(bh1, bh1); a2[1][1] = pk2(bh1, bh1);

        #pragma unroll 8
        for (int k = 0; k < 64; k++) {              // xt part
            float2 wv = *(const float2*)&sWh[k * 64 + c2base];
            double2 gd = *(const double2*)&sgx[k * GSL + rg4];
            ull ga = dl(gd.x), gb = dl(gd.y);
            ull W0 = pk2(wv.x, wv.x), W1 = pk2(wv.y, wv.y);
            ffma2(a2[0][0], ga, W0); ffma2(a2[0][1], gb, W0);
            ffma2(a2[1][0], ga, W1); ffma2(a2[1][1], gb, W1);
        }
        #pragma unroll 8
        for (int k = 0; k < 64; k++) {              // h*r part (weight rows 64+k)
            float2 wv = *(const float2*)&sWh[(64 + k) * 64 + c2base];
            double2 gd = *(const double2*)&sghr[k * GSL + rg4];
            ull ga = dl(gd.x), gb = dl(gd.y);
            ull W0 = pk2(wv.x, wv.x), W1 = pk2(wv.y, wv.y);
            ffma2(a2[0][0], ga, W0); ffma2(a2[0][1], gb, W0);
            ffma2(a2[1][0], ga, W1); ffma2(a2[1][1], gb, W1);
        }

        // ---- epilogue 2: tanh + blend; publish h and x_{t+1} ----
        float* sgxn = sm + (((t + 1) & 1) ? OFF_GX1 : OFF_GX0);
        #pragma unroll
        for (int j = 0; j < 2; j++) {
            int c = c2base + j;
            float2 p0 = upk2(a2[j][0]);
            float2 p1 = upk2(a2[j][1]);
            float hc0 = ftanh_(p0.x), hc1 = ftanh_(p0.y);
            float hc2 = ftanh_(p1.x), hc3 = ftanh_(p1.y);
            float4 z4 = *(const float4*)&szb[c * GSL + rg4];
            float4 h4 = *(const float4*)&shb[c * GSL + rg4];
            float4 hn = make_float4(fmaf(z4.x, hc0 - h4.x, h4.x),
                                    fmaf(z4.y, hc1 - h4.y, h4.y),
                                    fmaf(z4.z, hc2 - h4.z, h4.z),
                                    fmaf(z4.w, hc3 - h4.w, h4.w));
            *(float4*)&shb[c * GSL + rg4] = hn;
            *(float4*)&sgh[c * GSL + rg4] = hn;
            if (t < T2V - 1) {
                *(float4*)&sgxn[c * GSL + rg4] =
                    make_float4(xv[j][0], xv[j][1], xv[j][2], xv[j][3]);
            }
        }
        __syncthreads();   // state for step t+1 published
    }

    // ---- write h_final ----
    #pragma unroll
    for (int j = 0; j < 2; j++) {
        int c = c2base + j;
        float4 h4 = *(const float4*)&shb[c * GSL + rg4];
        out[(size_t)(row0 + rg4 + 0) * DV + c] = h4.x;
        out[(size_t)(row0 + rg4 + 1) * DV + c] = h4.y;
        out[(size_t)(row0 + rg4 + 2) * DV + c] = h4.z;
        out[(size_t)(row0 + rg4 + 3) * DV + c] = h4.w;
    }
}

extern "C" void kernel_launch(void* const* d_in, const int* in_sizes, int n_in,
                              void* d_out, int out_size) {
    const float* x  = (const float*)d_in[0];
    const float* kh = (const float*)d_in[1];
    const float* kr = (const float*)d_in[2];
    const float* kz = (const float*)d_in[3];
    const float* bh = (const float*)d_in[4];
    const float* br = (const float*)d_in[5];
    const float* bz = (const float*)d_in[6];
    float* out = (float*)d_out;

    static bool attr_set = false;
    if (!attr_set) {
        cudaFuncSetAttribute(gru4d_kernel,
                             cudaFuncAttributeMaxDynamicSharedMemorySize,
                             SMEM_BYTES);
        attr_set = true;
    }
    gru4d_kernel<<<NCTA, NT, SMEM_BYTES>>>(x, kh, kr, kz, bh, br, bz, out);
}